// round 9
// baseline (speedup 1.0000x reference)
#include <cuda_runtime.h>
#include <cstdint>

// MultiHeadAttention_5128190951704 — algebraic collapse:
//   softmax rows sum to 1 and the 'bnqk,bnvd->bnqd' einsum is separable in k/v,
//   so   y[b,o,d] = b_proj[o] + sum_n wp_sum[o,n] * sum_c wv_sum[n,c] * x[b,c,d]
// i.e. a rank-8 channel map per spatial position. Memory-bound: 256 MB traffic.

#define B_   16
#define C_   512
#define NH_  8
#define S_   4096          // H*W
#define TPB  128           // threads per block
#define POS_PER_BLOCK 256  // 2 positions (one f32x2) per thread

typedef unsigned long long ull;

// Scratch for folded weights (alloc-free rule: __device__ globals)
__device__ float g_wv[NH_ * C_];  // [n][c]  = sum of 64 V-rows of w_qkv per head
__device__ float g_wp[C_ * NH_];  // [o][n]  = sum of 64 proj columns per head

__device__ __forceinline__ ull dup2(float v) {
    ull r;
    asm("mov.b64 %0, {%1, %1};" : "=l"(r) : "r"(__float_as_uint(v)));
    return r;
}
__device__ __forceinline__ ull fma2(ull a, ull b, ull c) {
    ull d;
    asm("fma.rn.f32x2 %0, %1, %2, %3;" : "=l"(d) : "l"(a), "l"(b), "l"(c));
    return d;
}

// ---------------------------------------------------------------------------
// Prep: fold weights. 8192 outputs, each a 64-term sum. ~1 MB reads, trivial.
// ---------------------------------------------------------------------------
__global__ void prep_kernel(const float* __restrict__ wqkv,
                            const float* __restrict__ wproj) {
    int t = blockIdx.x * blockDim.x + threadIdx.x;
    if (t < NH_ * C_) {
        // wv_sum[n][c] = sum_j wqkv[2C + n*64 + j][c]
        int n = t >> 9, c = t & (C_ - 1);
        const float* p = wqkv + (size_t)(2 * C_ + n * 64) * C_ + c;
        float s = 0.f;
        #pragma unroll
        for (int j = 0; j < 64; j++) s += p[(size_t)j * C_];
        g_wv[n * C_ + c] = s;
    } else if (t < 2 * NH_ * C_) {
        // wp_sum[o][n] = sum_j wproj[o][n*64 + j]
        int u = t - NH_ * C_;
        int o = u >> 3, n = u & 7;
        const float* p = wproj + (size_t)o * C_ + n * 64;
        float s = 0.f;
        #pragma unroll
        for (int j = 0; j < 64; j++) s += p[j];
        g_wp[o * NH_ + n] = s;
    }
}

// ---------------------------------------------------------------------------
// Main fused kernel. Block = 128 threads x 2 positions (packed f32x2).
// Grid = 16 batches x 16 spatial tiles = 256 blocks.
// SMEM: duplicated-packed weights for FFMA2 (broadcast LDS, conflict-free).
//   s_wv2 [c][n] 32 KB | s_wp2 [o][n] 32 KB | s_b2 [o] 4 KB  = 68 KB dynamic.
// ---------------------------------------------------------------------------
#define SMEM_BYTES ((NH_ * C_ + C_ * NH_ + C_) * 8)  // 69632

__global__ void __launch_bounds__(TPB)
attn_main(const float* __restrict__ x,
          const float* __restrict__ bias,
          float* __restrict__ y) {
    extern __shared__ ull smem[];
    ull* s_wv2 = smem;                 // [c][n], c-major so per-c weights are contiguous
    ull* s_wp2 = smem + NH_ * C_;      // [o][n]
    ull* s_b2  = smem + 2 * NH_ * C_;  // [o]

    const int tid = threadIdx.x;
    for (int t = tid; t < NH_ * C_; t += TPB) {
        int c = t >> 3, n = t & 7;
        s_wv2[t] = dup2(g_wv[n * C_ + c]);  // transpose [n][c] -> [c][n]
        s_wp2[t] = dup2(g_wp[t]);
    }
    for (int t = tid; t < C_; t += TPB) s_b2[t] = dup2(bias[t]);
    __syncthreads();

    const int b     = blockIdx.x >> 4;
    const int tile  = blockIdx.x & 15;
    const int dbase = tile * POS_PER_BLOCK;

    // ---- Phase 1: acc[n] = sum_c wv_sum[n,c] * x[b,c,d0..d1]  (packed pair)
    const ull* xp = (const ull*)(x + (size_t)b * C_ * S_ + dbase) + tid;
    ull acc[NH_];
    #pragma unroll
    for (int n = 0; n < NH_; n++) acc[n] = 0ull;

    #pragma unroll 4
    for (int c = 0; c < C_; c++) {
        ull xv = xp[(size_t)c * (S_ / 2)];  // coalesced 8B/thread
        const ulonglong2* wv = (const ulonglong2*)(s_wv2 + c * 8);
        ulonglong2 w0 = wv[0], w1 = wv[1], w2 = wv[2], w3 = wv[3];
        acc[0] = fma2(w0.x, xv, acc[0]);
        acc[1] = fma2(w0.y, xv, acc[1]);
        acc[2] = fma2(w1.x, xv, acc[2]);
        acc[3] = fma2(w1.y, xv, acc[3]);
        acc[4] = fma2(w2.x, xv, acc[4]);
        acc[5] = fma2(w2.y, xv, acc[5]);
        acc[6] = fma2(w3.x, xv, acc[6]);
        acc[7] = fma2(w3.y, xv, acc[7]);
    }

    // ---- Phase 2: y[b,o,d] = b[o] + sum_n wp_sum[o,n] * acc[n]
    ull* yp = (ull*)(y + (size_t)b * C_ * S_ + dbase) + tid;
    #pragma unroll 2
    for (int o = 0; o < C_; o++) {
        ull r = s_b2[o];
        const ulonglong2* wp = (const ulonglong2*)(s_wp2 + o * 8);
        ulonglong2 w0 = wp[0], w1 = wp[1], w2 = wp[2], w3 = wp[3];
        r = fma2(w0.x, acc[0], r);
        r = fma2(w0.y, acc[1], r);
        r = fma2(w1.x, acc[2], r);
        r = fma2(w1.y, acc[3], r);
        r = fma2(w2.x, acc[4], r);
        r = fma2(w2.y, acc[5], r);
        r = fma2(w3.x, acc[6], r);
        r = fma2(w3.y, acc[7], r);
        yp[(size_t)o * (S_ / 2)] = r;   // coalesced STG.64
    }
}

// ---------------------------------------------------------------------------
extern "C" void kernel_launch(void* const* d_in, const int* in_sizes, int n_in,
                              void* d_out, int out_size) {
    const float* x     = (const float*)d_in[0];
    const float* wqkv  = (const float*)d_in[1];
    const float* wproj = (const float*)d_in[2];
    const float* bproj = (const float*)d_in[3];
    float* y = (float*)d_out;

    cudaFuncSetAttribute(attn_main, cudaFuncAttributeMaxDynamicSharedMemorySize,
                         SMEM_BYTES);

    prep_kernel<<<32, 256>>>(wqkv, wproj);
    attn_main<<<B_ * (S_ / POS_PER_BLOCK), TPB, SMEM_BYTES>>>(x, bproj, y);
}

// round 10
// speedup vs baseline: 1.0012x; 1.0012x over previous
#include <cuda_runtime.h>
#include <cstdint>

// MultiHeadAttention_5128190951704 — algebraic collapse:
//   softmax rows sum to 1 and the 'bnqk,bnvd->bnqd' einsum is separable in k/v,
//   so   y[b,o,d] = b_proj[o] + sum_n wp_sum[o,n] * sum_c wv_sum[n,c] * x[b,c,d]
// i.e. a rank-8 channel map per spatial position. Memory-bound: 256 MB traffic.

#define B_   16
#define C_   512
#define NH_  8
#define S_   4096          // H*W
#define TPB  128           // threads per block
#define POS_PER_BLOCK 256  // 2 positions (one f32x2) per thread

typedef unsigned long long ull;

// Scratch for folded weights (alloc-free rule: __device__ globals)
__device__ float g_wv[NH_ * C_];  // [n][c]  = sum of 64 V-rows of w_qkv per head
__device__ float g_wp[C_ * NH_];  // [o][n]  = sum of 64 proj columns per head

__device__ __forceinline__ ull dup2(float v) {
    ull r;
    asm("mov.b64 %0, {%1, %1};" : "=l"(r) : "r"(__float_as_uint(v)));
    return r;
}
__device__ __forceinline__ ull fma2(ull a, ull b, ull c) {
    ull d;
    asm("fma.rn.f32x2 %0, %1, %2, %3;" : "=l"(d) : "l"(a), "l"(b), "l"(c));
    return d;
}

// ---------------------------------------------------------------------------
// Prep: fold weights. 8192 outputs, each a 64-term sum. ~1 MB reads, trivial.
// ---------------------------------------------------------------------------
__global__ void prep_kernel(const float* __restrict__ wqkv,
                            const float* __restrict__ wproj) {
    int t = blockIdx.x * blockDim.x + threadIdx.x;
    if (t < NH_ * C_) {
        // wv_sum[n][c] = sum_j wqkv[2C + n*64 + j][c]
        int n = t >> 9, c = t & (C_ - 1);
        const float* p = wqkv + (size_t)(2 * C_ + n * 64) * C_ + c;
        float s = 0.f;
        #pragma unroll
        for (int j = 0; j < 64; j++) s += p[(size_t)j * C_];
        g_wv[n * C_ + c] = s;
    } else if (t < 2 * NH_ * C_) {
        // wp_sum[o][n] = sum_j wproj[o][n*64 + j]
        int u = t - NH_ * C_;
        int o = u >> 3, n = u & 7;
        const float* p = wproj + (size_t)o * C_ + n * 64;
        float s = 0.f;
        #pragma unroll
        for (int j = 0; j < 64; j++) s += p[j];
        g_wp[o * NH_ + n] = s;
    }
}

// ---------------------------------------------------------------------------
// Main fused kernel. Block = 128 threads x 2 positions (packed f32x2).
// Grid = 16 batches x 16 spatial tiles = 256 blocks.
// SMEM: duplicated-packed weights for FFMA2 (broadcast LDS, conflict-free).
//   s_wv2 [c][n] 32 KB | s_wp2 [o][n] 32 KB | s_b2 [o] 4 KB  = 68 KB dynamic.
// ---------------------------------------------------------------------------
#define SMEM_BYTES ((NH_ * C_ + C_ * NH_ + C_) * 8)  // 69632

__global__ void __launch_bounds__(TPB)
attn_main(const float* __restrict__ x,
          const float* __restrict__ bias,
          float* __restrict__ y) {
    extern __shared__ ull smem[];
    ull* s_wv2 = smem;                 // [c][n], c-major so per-c weights are contiguous
    ull* s_wp2 = smem + NH_ * C_;      // [o][n]
    ull* s_b2  = smem + 2 * NH_ * C_;  // [o]

    const int tid = threadIdx.x;
    for (int t = tid; t < NH_ * C_; t += TPB) {
        int c = t >> 3, n = t & 7;
        s_wv2[t] = dup2(g_wv[n * C_ + c]);  // transpose [n][c] -> [c][n]
        s_wp2[t] = dup2(g_wp[t]);
    }
    for (int t = tid; t < C_; t += TPB) s_b2[t] = dup2(bias[t]);
    __syncthreads();

    const int b     = blockIdx.x >> 4;
    const int tile  = blockIdx.x & 15;
    const int dbase = tile * POS_PER_BLOCK;

    // ---- Phase 1: acc[n] = sum_c wv_sum[n,c] * x[b,c,d0..d1]  (packed pair)
    const ull* xp = (const ull*)(x + (size_t)b * C_ * S_ + dbase) + tid;
    ull acc[NH_];
    #pragma unroll
    for (int n = 0; n < NH_; n++) acc[n] = 0ull;

    #pragma unroll 4
    for (int c = 0; c < C_; c++) {
        ull xv = xp[(size_t)c * (S_ / 2)];  // coalesced 8B/thread
        const ulonglong2* wv = (const ulonglong2*)(s_wv2 + c * 8);
        ulonglong2 w0 = wv[0], w1 = wv[1], w2 = wv[2], w3 = wv[3];
        acc[0] = fma2(w0.x, xv, acc[0]);
        acc[1] = fma2(w0.y, xv, acc[1]);
        acc[2] = fma2(w1.x, xv, acc[2]);
        acc[3] = fma2(w1.y, xv, acc[3]);
        acc[4] = fma2(w2.x, xv, acc[4]);
        acc[5] = fma2(w2.y, xv, acc[5]);
        acc[6] = fma2(w3.x, xv, acc[6]);
        acc[7] = fma2(w3.y, xv, acc[7]);
    }

    // ---- Phase 2: y[b,o,d] = b[o] + sum_n wp_sum[o,n] * acc[n]
    ull* yp = (ull*)(y + (size_t)b * C_ * S_ + dbase) + tid;
    #pragma unroll 2
    for (int o = 0; o < C_; o++) {
        ull r = s_b2[o];
        const ulonglong2* wp = (const ulonglong2*)(s_wp2 + o * 8);
        ulonglong2 w0 = wp[0], w1 = wp[1], w2 = wp[2], w3 = wp[3];
        r = fma2(w0.x, acc[0], r);
        r = fma2(w0.y, acc[1], r);
        r = fma2(w1.x, acc[2], r);
        r = fma2(w1.y, acc[3], r);
        r = fma2(w2.x, acc[4], r);
        r = fma2(w2.y, acc[5], r);
        r = fma2(w3.x, acc[6], r);
        r = fma2(w3.y, acc[7], r);
        yp[(size_t)o * (S_ / 2)] = r;   // coalesced STG.64
    }
}

// ---------------------------------------------------------------------------
extern "C" void kernel_launch(void* const* d_in, const int* in_sizes, int n_in,
                              void* d_out, int out_size) {
    const float* x     = (const float*)d_in[0];
    const float* wqkv  = (const float*)d_in[1];
    const float* wproj = (const float*)d_in[2];
    const float* bproj = (const float*)d_in[3];
    float* y = (float*)d_out;

    cudaFuncSetAttribute(attn_main, cudaFuncAttributeMaxDynamicSharedMemorySize,
                         SMEM_BYTES);

    prep_kernel<<<32, 256>>>(wqkv, wproj);
    attn_main<<<B_ * (S_ / POS_PER_BLOCK), TPB, SMEM_BYTES>>>(x, bproj, y);
}